// round 6
// baseline (speedup 1.0000x reference)
#include <cuda_runtime.h>
#include <cuda_bf16.h>
#include <cstdint>
#include <cfloat>

#define B_    64
#define N_    512
#define BN_   32768
#define K_    8
#define H_    336
#define C_    256
#define CAT_  1030

// ---------------- scratch (static device memory) ----------------
__device__ float g_xo[4 * BN_ * C_];
__device__ float g_dist[(size_t)B_ * N_ * N_];
__device__ int   g_knn[BN_ * K_];
__device__ float g_ab[(size_t)BN_ * 672];
__device__ float g_bcomb[672];
__device__ float g_cat[(size_t)BN_ * CAT_];
__device__ float g_t[(size_t)BN_ * H_];
__device__ float g_m[(size_t)BN_ * C_];
__device__ float g_norm[BN_];
__device__ float g_pool[B_ * C_];
__device__ __nv_bfloat16 g_bh1[672 * 1088];   // 672x256 (ab) / 336x1088 (mlp1)
__device__ __nv_bfloat16 g_bl1[672 * 1088];
__device__ __nv_bfloat16 g_bh2[256 * 384];
__device__ __nv_bfloat16 g_bl2[256 * 384];

__device__ __forceinline__ float lrelu(float v) { return v >= 0.f ? v : 0.01f * v; }
// swizzled in-tile byte offset for (row, byte) with 128B rows
__device__ __forceinline__ uint32_t sofs(int row, int b) {
    return (uint32_t)(row * 128 + (b ^ ((row & 7) << 4)));
}
__device__ __forceinline__ uint32_t smem_u32(const void* p) {
    uint32_t a;
    asm("{ .reg .u64 t; cvta.to.shared.u64 t, %1; cvt.u32.u64 %0, t; }" : "=r"(a) : "l"(p));
    return a;
}
__device__ __forceinline__ void ldsm4(uint32_t r[4], uint32_t addr) {
    asm volatile("ldmatrix.sync.aligned.m8n8.x4.shared.b16 {%0,%1,%2,%3}, [%4];"
                 : "=r"(r[0]), "=r"(r[1]), "=r"(r[2]), "=r"(r[3]) : "r"(addr));
}
__device__ __forceinline__ void mma_bf16(float c[4], const uint32_t a[4],
                                         uint32_t b0, uint32_t b1) {
    asm volatile(
        "mma.sync.aligned.m16n8k16.row.col.f32.bf16.bf16.f32 "
        "{%0,%1,%2,%3}, {%4,%5,%6,%7}, {%8,%9}, {%0,%1,%2,%3};"
        : "+f"(c[0]), "+f"(c[1]), "+f"(c[2]), "+f"(c[3])
        : "r"(a[0]), "r"(a[1]), "r"(a[2]), "r"(a[3]), "r"(b0), "r"(b1));
}
// split 8 fp32 -> hi/lo bf16, store 16B each, swizzled
__device__ __forceinline__ void store8(char* sh, char* sl, int row, int colbyte,
                                       const float* v) {
    alignas(16) __nv_bfloat16 h[8];
    alignas(16) __nv_bfloat16 l[8];
#pragma unroll
    for (int q = 0; q < 8; ++q) {
        h[q] = __float2bfloat16(v[q]);
        l[q] = __float2bfloat16(v[q] - __bfloat162float(h[q]));
    }
    uint32_t so = sofs(row, colbyte);
    *reinterpret_cast<uint4*>(sh + so) = *reinterpret_cast<const uint4*>(h);
    *reinterpret_cast<uint4*>(sl + so) = *reinterpret_cast<const uint4*>(l);
}

// ---------------- unified warp-MMA GEMM ----------------
// D[m][n] = sum_k A[m][k]*B[n][k], fp32 accum, 3-product bf16 split precision.
// Tile M=128, N=128, K-chunks of 64, double-buffered smem. 8 warps = 2(M)x4(N),
// each warp 64x32.
// ASRC: 0 direct fp32 A rows (stride aK); 1 gather lrelu(ab_i + ab_j) via knn.
// BSPLIT: 1 B pre-split bf16 [n][bK]; 0 B direct fp32 rows (BF, stride bK).
// EPI: 0 plain bias(+act); 1 max over 8 edge rows -> out[node][256]; 2 distance.
#define SMEM_SZ 131072
template <int ASRC, int BSPLIT, int EPI, int ACT>
__global__ __launch_bounds__(256)
void tc_gemm(const float* __restrict__ A, int aK,
             const int* __restrict__ knn,
             const __nv_bfloat16* __restrict__ BH, const __nv_bfloat16* __restrict__ BL,
             const float* __restrict__ BF, int bK,
             const float* __restrict__ bias, const float* __restrict__ nrm,
             float* __restrict__ out, int ldOut,
             int Ntot, int Kmax, int nch, int zRows) {
    extern __shared__ char smem[];
    const uint32_t sbase = smem_u32(smem);
    const int tid = threadIdx.x, wid = tid >> 5, lane = tid & 31;
    const int warpM = wid & 1, warpN = wid >> 1;
    const int m0 = blockIdx.y * 128;
    const int n0 = blockIdx.x * 128;
    const int rbase = blockIdx.z * zRows;
    const int Ntile = min(128, Ntot - n0);

    // A loader: 2 threads/row, 32 k each
    const int arow = tid >> 1, acb = (tid & 1) * 32;
    const float* aP0;
    const float* aP1 = nullptr;
    if constexpr (ASRC == 1) {
        int e = m0 + arow;
        int i = e >> 3;
        int j = __ldg(&knn[e]);
        aP0 = A + (size_t)i * 672;
        aP1 = A + (size_t)j * 672 + 336;
    } else {
        aP0 = A + (size_t)(rbase + m0 + arow) * aK;
    }
    // B loader: 2 threads/row, 32 k each
    const int brow = tid >> 1, bcb = (tid & 1) * 32;

    float acc[4][4][4];
#pragma unroll
    for (int a = 0; a < 4; ++a)
#pragma unroll
        for (int b = 0; b < 4; ++b)
#pragma unroll
            for (int c = 0; c < 4; ++c) acc[a][b][c] = 0.f;

    float vA[32];
    float vBf[32];
    uint4 vBh[4], vBl[4];

    auto prefetch = [&](int c) {
        const int k0 = c * 64;
#pragma unroll
        for (int g = 0; g < 4; ++g)
#pragma unroll
            for (int q = 0; q < 8; ++q) {
                int k = k0 + acb + g * 8 + q;
                float val = 0.f;
                if (k < Kmax) {
                    if constexpr (ASRC == 1) val = lrelu(aP0[k] + aP1[k]);
                    else val = aP0[k];
                }
                vA[g * 8 + q] = val;
            }
        if constexpr (BSPLIT == 1) {
            if (brow < Ntile) {
                const __nv_bfloat16* ph = BH + (size_t)(n0 + brow) * bK + k0 + bcb;
                const __nv_bfloat16* pl = BL + (size_t)(n0 + brow) * bK + k0 + bcb;
#pragma unroll
                for (int g = 0; g < 4; ++g) {
                    vBh[g] = *reinterpret_cast<const uint4*>(ph + g * 8);
                    vBl[g] = *reinterpret_cast<const uint4*>(pl + g * 8);
                }
            } else {
#pragma unroll
                for (int g = 0; g < 4; ++g) {
                    vBh[g] = make_uint4(0, 0, 0, 0);
                    vBl[g] = make_uint4(0, 0, 0, 0);
                }
            }
        } else {
            const float* pb = BF + (size_t)(rbase + n0 + brow) * bK;
#pragma unroll
            for (int g = 0; g < 4; ++g)
#pragma unroll
                for (int q = 0; q < 8; ++q) {
                    int k = k0 + bcb + g * 8 + q;
                    vBf[g * 8 + q] = (k < Kmax) ? pb[k] : 0.f;
                }
        }
    };
    auto sts = [&](int buf) {
        char* base = smem + buf * 65536;
        char* sAh = base;
        char* sAl = base + 16384;
        char* sBh = base + 32768;
        char* sBl = base + 49152;
#pragma unroll
        for (int g = 0; g < 4; ++g)
            store8(sAh, sAl, arow, (acb + g * 8) * 2, &vA[g * 8]);
        if constexpr (BSPLIT == 1) {
#pragma unroll
            for (int g = 0; g < 4; ++g) {
                uint32_t so = sofs(brow, (bcb + g * 8) * 2);
                *reinterpret_cast<uint4*>(sBh + so) = vBh[g];
                *reinterpret_cast<uint4*>(sBl + so) = vBl[g];
            }
        } else {
#pragma unroll
            for (int g = 0; g < 4; ++g)
                store8(sBh, sBl, brow, (bcb + g * 8) * 2, &vBf[g * 8]);
        }
    };

    prefetch(0);
    sts(0);
    __syncthreads();

    const int lr = lane & 15, lk = (lane >> 4) * 16;
    for (int c = 0; c < nch; ++c) {
        if (c + 1 < nch) prefetch(c + 1);
        const uint32_t bb = sbase + (c & 1) * 65536;
        const uint32_t sAh = bb, sAl = bb + 16384, sBh = bb + 32768, sBl = bb + 49152;
#pragma unroll
        for (int ks = 0; ks < 4; ++ks) {
            const int kb = ks * 32 + lk;
            uint32_t ah[4][4], al[4][4], bh[2][4], bl[2][4];
#pragma unroll
            for (int mt = 0; mt < 4; ++mt) {
                int row = warpM * 64 + mt * 16 + lr;
                uint32_t o = sofs(row, kb);
                ldsm4(ah[mt], sAh + o);
                ldsm4(al[mt], sAl + o);
            }
#pragma unroll
            for (int nt = 0; nt < 2; ++nt) {
                int row = warpN * 32 + nt * 16 + lr;
                uint32_t o = sofs(row, kb);
                ldsm4(bh[nt], sBh + o);
                ldsm4(bl[nt], sBl + o);
            }
#pragma unroll
            for (int mt = 0; mt < 4; ++mt)
#pragma unroll
                for (int nt8 = 0; nt8 < 4; ++nt8) {
                    int nt16 = nt8 >> 1, s = nt8 & 1;
                    mma_bf16(acc[mt][nt8], ah[mt], bh[nt16][s], bh[nt16][s + 2]);
                    mma_bf16(acc[mt][nt8], ah[mt], bl[nt16][s], bl[nt16][s + 2]);
                    mma_bf16(acc[mt][nt8], al[mt], bh[nt16][s], bh[nt16][s + 2]);
                }
        }
        if (c + 1 < nch) sts((c + 1) & 1);
        __syncthreads();
    }

    // ---------------- epilogue ----------------
    if constexpr (EPI == 1) {
        // rows are edges; 8 consecutive rows = 1 node. m16 tile = 2 nodes.
#pragma unroll
        for (int mt = 0; mt < 4; ++mt) {
            int nodeA = (m0 + warpM * 64 + mt * 16) >> 3;
#pragma unroll
            for (int nt8 = 0; nt8 < 4; ++nt8) {
                float c0 = acc[mt][nt8][0], c1 = acc[mt][nt8][1];
                float c2 = acc[mt][nt8][2], c3 = acc[mt][nt8][3];
#pragma unroll
                for (int m = 4; m <= 16; m <<= 1) {
                    c0 = fmaxf(c0, __shfl_xor_sync(0xffffffffu, c0, m));
                    c1 = fmaxf(c1, __shfl_xor_sync(0xffffffffu, c1, m));
                    c2 = fmaxf(c2, __shfl_xor_sync(0xffffffffu, c2, m));
                    c3 = fmaxf(c3, __shfl_xor_sync(0xffffffffu, c3, m));
                }
                if (lane < 4) {
                    int n = n0 + warpN * 32 + nt8 * 8 + lane * 2;
                    float b0 = bias[n], b1 = bias[n + 1];
                    float2 e0 = make_float2(lrelu(c0 + b0), lrelu(c1 + b1));
                    float2 e1 = make_float2(lrelu(c2 + b0), lrelu(c3 + b1));
                    *reinterpret_cast<float2*>(out + (size_t)nodeA * 256 + n) = e0;
                    *reinterpret_cast<float2*>(out + (size_t)(nodeA + 1) * 256 + n) = e1;
                }
            }
        }
    } else {
#pragma unroll
        for (int mt = 0; mt < 4; ++mt) {
            int r0 = rbase + m0 + warpM * 64 + mt * 16 + (lane >> 2);
#pragma unroll
            for (int nt8 = 0; nt8 < 4; ++nt8) {
                int n = n0 + warpN * 32 + nt8 * 8 + (lane & 3) * 2;
                if (n >= Ntot) continue;
                if constexpr (EPI == 2) {
                    float ni0 = nrm[r0], ni1 = nrm[r0 + 8];
                    float nj0 = nrm[rbase + n], nj1 = nrm[rbase + n + 1];
                    float2 e0 = make_float2(ni0 + nj0 - 2.f * acc[mt][nt8][0],
                                            ni0 + nj1 - 2.f * acc[mt][nt8][1]);
                    float2 e1 = make_float2(ni1 + nj0 - 2.f * acc[mt][nt8][2],
                                            ni1 + nj1 - 2.f * acc[mt][nt8][3]);
                    *reinterpret_cast<float2*>(out + (size_t)r0 * ldOut + n) = e0;
                    *reinterpret_cast<float2*>(out + (size_t)(r0 + 8) * ldOut + n) = e1;
                } else {
                    float b0 = bias[n], b1 = bias[n + 1];
                    float v0 = acc[mt][nt8][0] + b0, v1 = acc[mt][nt8][1] + b1;
                    float v2 = acc[mt][nt8][2] + b0, v3 = acc[mt][nt8][3] + b1;
                    if (ACT) { v0 = lrelu(v0); v1 = lrelu(v1); v2 = lrelu(v2); v3 = lrelu(v3); }
                    *reinterpret_cast<float2*>(out + (size_t)r0 * ldOut + n) =
                        make_float2(v0, v1);
                    *reinterpret_cast<float2*>(out + (size_t)(r0 + 8) * ldOut + n) =
                        make_float2(v2, v3);
                }
            }
        }
    }
}

// ---------------- weight split kernels (transpose to [n][Kpad], hi/lo) ----------------
__global__ void splitw_kernel(const float* __restrict__ W, __nv_bfloat16* __restrict__ bh,
                              __nv_bfloat16* __restrict__ bl, int K, int N, int Kpad) {
    int idx = blockIdx.x * blockDim.x + threadIdx.x;
    if (idx >= N * Kpad) return;
    int n = idx / Kpad, k = idx % Kpad;
    float v = (k < K) ? W[(size_t)k * N + n] : 0.f;
    __nv_bfloat16 h = __float2bfloat16(v);
    bh[idx] = h;
    bl[idx] = __float2bfloat16(v - __bfloat162float(h));
}

__global__ void splitw1_kernel(const float* __restrict__ w1, const float* __restrict__ b1,
                               __nv_bfloat16* __restrict__ bh, __nv_bfloat16* __restrict__ bl,
                               float* __restrict__ bcomb, int F, int Kpad) {
    int idx = blockIdx.x * blockDim.x + threadIdx.x;
    if (idx < 672) bcomb[idx] = (idx < H_) ? b1[idx] : 0.f;
    if (idx >= 672 * Kpad) return;
    int n = idx / Kpad, f = idx % Kpad;
    float v = 0.f;
    if (f < F)
        v = (n < H_) ? (w1[f * H_ + n] - w1[(F + f) * H_ + n])
                     : w1[(F + f) * H_ + (n - H_)];
    __nv_bfloat16 h = __float2bfloat16(v);
    bh[idx] = h;
    bl[idx] = __float2bfloat16(v - __bfloat162float(h));
}

// ---------------- small kernels ----------------
__global__ void norm_kernel(const float* __restrict__ x, float* __restrict__ nrm, int F) {
    int i = blockIdx.x * blockDim.x + threadIdx.x;
    if (i >= BN_) return;
    const float* r = x + (size_t)i * F;
    float s = 0.f;
    for (int f = 0; f < F; ++f) { float v = r[f]; s += v * v; }
    nrm[i] = s;
}

__global__ void topk_kernel(const float* __restrict__ D, int* __restrict__ knn) {
    int gid = blockIdx.x * blockDim.x + threadIdx.x;
    if (gid >= BN_) return;
    const float* row = D + (size_t)gid * N_;
    float kd[K_];
    int ki[K_];
#pragma unroll
    for (int k = 0; k < K_; ++k) { kd[k] = FLT_MAX; ki[k] = -1; }
    for (int j = 0; j < N_; ++j) {
        float d = row[j];
        if (d < kd[K_ - 1]) {
            int p = K_ - 1;
            while (p > 0 && kd[p - 1] > d) { kd[p] = kd[p - 1]; ki[p] = ki[p - 1]; --p; }
            kd[p] = d;
            ki[p] = j;
        }
    }
    int b = gid / N_;
#pragma unroll
    for (int k = 0; k < K_; ++k) knn[gid * K_ + k] = b * N_ + ki[k];
}

__global__ void concat_kernel(const float* __restrict__ x, const float* __restrict__ x1,
                              const float* __restrict__ x2, const float* __restrict__ x3,
                              const float* __restrict__ x4, float* __restrict__ cat) {
    int idx = blockIdx.x * blockDim.x + threadIdx.x;
    if (idx >= BN_ * CAT_) return;
    int i = idx / CAT_, f = idx % CAT_;
    float v;
    if (f < 6) {
        v = x[i * 6 + f];
    } else {
        int g = f - 6;
        int l = g >> 8, c = g & 255;
        const float* src = (l == 0) ? x1 : (l == 1) ? x2 : (l == 2) ? x3 : x4;
        v = src[(size_t)i * C_ + c];
    }
    cat[idx] = v;
}

__global__ void pool_kernel(const float* __restrict__ m, float* __restrict__ g) {
    int b = blockIdx.x, c = threadIdx.x;
    float s = 0.f;
    for (int n = 0; n < N_; ++n) s += m[(size_t)(b * N_ + n) * C_ + c];
    g[b * C_ + c] = s * (1.f / (float)N_);
}

__global__ void head_kernel(const float* __restrict__ g, const float* __restrict__ w1,
                            const float* __restrict__ b1, const float* __restrict__ w2,
                            const float* __restrict__ b2, float* __restrict__ out) {
    __shared__ float sg[256];
    __shared__ float sh[128];
    int b = blockIdx.x, t = threadIdx.x;
    sg[t] = g[b * 256 + t];
    sg[t + 128] = g[b * 256 + 128 + t];
    __syncthreads();
    float s = b1[t];
    for (int f = 0; f < 256; ++f) s += sg[f] * w1[f * 128 + t];
    sh[t] = lrelu(s);
    __syncthreads();
    if (t < 3) {
        float o = b2[t];
        for (int c = 0; c < 128; ++c) o += sh[c] * w2[c * 3 + t];
        out[b * 3 + t] = o;
    }
}

// ---------------- host ----------------
extern "C" void kernel_launch(void* const* d_in, const int* in_sizes, int n_in,
                              void* d_out, int out_size) {
    const float* x = (const float*)d_in[0];
    const float *cw1[4], *cb1[4], *cw2[4], *cb2[4];
    for (int L = 0; L < 4; ++L) {
        cw1[L] = (const float*)d_in[3 + 4 * L];
        cb1[L] = (const float*)d_in[4 + 4 * L];
        cw2[L] = (const float*)d_in[5 + 4 * L];
        cb2[L] = (const float*)d_in[6 + 4 * L];
    }
    const float* m1w1 = (const float*)d_in[19];
    const float* m1b1 = (const float*)d_in[20];
    const float* m1w2 = (const float*)d_in[21];
    const float* m1b2 = (const float*)d_in[22];
    const float* m2w1 = (const float*)d_in[23];
    const float* m2b1 = (const float*)d_in[24];
    const float* m2w2 = (const float*)d_in[25];
    const float* m2b2 = (const float*)d_in[26];
    float* out = (float*)d_out;

    float *p_xo, *p_d, *p_ab, *p_bc, *p_cat, *p_t, *p_m, *p_nrm, *p_pool;
    int* p_knn;
    __nv_bfloat16 *p_bh1, *p_bl1, *p_bh2, *p_bl2;
    cudaGetSymbolAddress((void**)&p_xo, g_xo);
    cudaGetSymbolAddress((void**)&p_d, g_dist);
    cudaGetSymbolAddress((void**)&p_knn, g_knn);
    cudaGetSymbolAddress((void**)&p_ab, g_ab);
    cudaGetSymbolAddress((void**)&p_bc, g_bcomb);
    cudaGetSymbolAddress((void**)&p_cat, g_cat);
    cudaGetSymbolAddress((void**)&p_t, g_t);
    cudaGetSymbolAddress((void**)&p_m, g_m);
    cudaGetSymbolAddress((void**)&p_nrm, g_norm);
    cudaGetSymbolAddress((void**)&p_pool, g_pool);
    cudaGetSymbolAddress((void**)&p_bh1, g_bh1);
    cudaGetSymbolAddress((void**)&p_bl1, g_bl1);
    cudaGetSymbolAddress((void**)&p_bh2, g_bh2);
    cudaGetSymbolAddress((void**)&p_bl2, g_bl2);

    cudaFuncSetAttribute(tc_gemm<0, 0, 2, 0>, cudaFuncAttributeMaxDynamicSharedMemorySize, SMEM_SZ);
    cudaFuncSetAttribute(tc_gemm<0, 1, 0, 0>, cudaFuncAttributeMaxDynamicSharedMemorySize, SMEM_SZ);
    cudaFuncSetAttribute(tc_gemm<1, 1, 1, 1>, cudaFuncAttributeMaxDynamicSharedMemorySize, SMEM_SZ);
    cudaFuncSetAttribute(tc_gemm<0, 1, 0, 1>, cudaFuncAttributeMaxDynamicSharedMemorySize, SMEM_SZ);

    float* xL[4];
    for (int L = 0; L < 4; ++L) xL[L] = p_xo + (size_t)L * BN_ * C_;

    for (int L = 0; L < 4; ++L) {
        const float* xin = (L == 0) ? x : xL[L - 1];
        int F = (L == 0) ? 6 : C_;
        int Kpad1 = (F == 6) ? 64 : 256;

        norm_kernel<<<BN_ / 256, 256>>>(xin, p_nrm, F);
        // distance GEMM on tensor cores (split precision): per-graph 512x512
        tc_gemm<0, 0, 2, 0><<<dim3(4, 4, B_), 256, SMEM_SZ>>>(
            xin, F, nullptr, nullptr, nullptr, xin, F, nullptr, p_nrm,
            p_d, N_, N_, F, (F + 63) / 64, N_);
        topk_kernel<<<BN_ / 256, 256>>>(p_d, p_knn);
        splitw1_kernel<<<(672 * Kpad1 + 255) / 256, 256>>>(cw1[L], cb1[L], p_bh1, p_bl1,
                                                           p_bc, F, Kpad1);
        // per-node a|b : [BN, F] @ [F, 672]
        tc_gemm<0, 1, 0, 0><<<dim3(6, BN_ / 128, 1), 256, SMEM_SZ>>>(
            xin, F, nullptr, p_bh1, p_bl1, nullptr, Kpad1, p_bc, nullptr,
            p_ab, 672, 672, F, Kpad1 / 64, 0);
        splitw_kernel<<<(256 * 384 + 255) / 256, 256>>>(cw2[L], p_bh2, p_bl2, H_, C_, 384);
        // fused edge gemm: gather lrelu(a_i+b_j), [BN*K,336]@[336,256], max over K, lrelu
        tc_gemm<1, 1, 1, 1><<<dim3(2, (BN_ * K_) / 128, 1), 256, SMEM_SZ>>>(
            p_ab, 672, p_knn, p_bh2, p_bl2, nullptr, 384, cb2[L], nullptr,
            xL[L], 256, 256, H_, 6, 0);
    }

    concat_kernel<<<(BN_ * CAT_ + 255) / 256, 256>>>(x, xL[0], xL[1], xL[2], xL[3], p_cat);
    splitw_kernel<<<(336 * 1088 + 255) / 256, 256>>>(m1w1, p_bh1, p_bl1, CAT_, H_, 1088);
    tc_gemm<0, 1, 0, 1><<<dim3(3, BN_ / 128, 1), 256, SMEM_SZ>>>(
        p_cat, CAT_, nullptr, p_bh1, p_bl1, nullptr, 1088, m1b1, nullptr,
        p_t, H_, H_, CAT_, 17, 0);
    splitw_kernel<<<(256 * 384 + 255) / 256, 256>>>(m1w2, p_bh2, p_bl2, H_, C_, 384);
    tc_gemm<0, 1, 0, 1><<<dim3(2, BN_ / 128, 1), 256, SMEM_SZ>>>(
        p_t, H_, nullptr, p_bh2, p_bl2, nullptr, 384, m1b2, nullptr,
        p_m, C_, C_, H_, 6, 0);
    pool_kernel<<<B_, 256>>>(p_m, p_pool);
    head_kernel<<<B_, 128>>>(p_pool, m2w1, m2b1, m2w2, m2b2, out);
}